// round 15
// baseline (speedup 1.0000x reference)
#include <cuda_runtime.h>
#include <math.h>

#define COMMIT_SCALE 1.25f   // 1 + COMMITMENT_COST; e_latent == q_latent in forward
#define EPS 1e-6f

#define LUT_SIZE 262144      // taxid range [0, 2E) = [0, 100000)
#define E_MAX    50016
#define INTMAX_I 0x7FFFFFFF

// One resident wave: 148 SMs x 8 blocks (regs=32 -> 8 x 256thr resident/SM).
// On 152-SM GB300 this is still a single wave.
#define MAIN_BLOCKS 1184

// g_lut: 0-as-empty encoding (stored = INT_MAX - idx; atomicMax == lower_bound).
// Zero-init at module load; idempotent across graph replays.
__device__ int    g_lut[LUT_SIZE];
__device__ float  g_qcache[E_MAX * 65];   // [E][65] = exact masked output row
__device__ double g_loss_sum;             // reset by finalize each replay
__device__ int    g_valid_cnt;
__device__ unsigned g_done;               // monotonic last-block ticket

__device__ __forceinline__ float tanh_approx(float x) {
    float r;
    asm("tanh.approx.f32 %0, %1;" : "=f"(r) : "f"(x));
    return r;
}

// ---------------- K1: codebook (approx transcendentals) + key scatter ----------------
__global__ void __launch_bounds__(256) vq_codebook_kernel(
    const float* __restrict__ emb, const int* __restrict__ key, int E)
{
    const int tid = blockIdx.x * blockDim.x + threadIdx.x;
    const int nth = gridDim.x * blockDim.x;

    for (int i = tid; i < E; i += nth) {
        int v = key[i];
        if (v >= 0 && v < LUT_SIZE) atomicMax(&g_lut[v], INTMAX_I - i);
    }

    const int lane = threadIdx.x & 31;
    const int gw = tid >> 5, nw = nth >> 5;
    for (int e = gw; e < E; e += nw) {
        const float wA = __ldg(&emb[(size_t)e * 64 + lane]);
        const float wB = __ldg(&emb[(size_t)e * 64 + lane + 32]);
        const float xA = 3.0f * tanh_approx(wA);
        const float xB = 3.0f * tanh_approx(wB);

        float s = xA * xA + xB * xB;
        #pragma unroll
        for (int off = 16; off; off >>= 1)
            s += __shfl_xor_sync(0xFFFFFFFFu, s, off);

        float n = sqrtf(fmaxf(s, EPS));
        n = fminf(n, 10.0f);
        const float en  = __expf(n);
        const float emn = __fdividef(1.0f, en);
        const float ch  = 0.5f * (en + emn);
        const float sh  = __fdividef(0.5f * (en - emn), n);

        float* q = g_qcache + (size_t)e * 65;
        if (lane == 0) q[0] = ch;
        q[1 + lane]  = sh * xA;
        q[33 + lane] = sh * xB;
    }
}

// ---------------- K2: main — 4-row subtiles + compact transpose-reduce ----------------
__global__ void __launch_bounds__(256, 7) vq_main_kernel(
    const float* __restrict__ inputs,    // [N, 65]
    const int*   __restrict__ lineages,  // [N, 2]
    float*       __restrict__ dout,      // [0]=loss, +1 = quantized_all
    int N, int E)
{
    const int lane        = threadIdx.x & 31;
    const int warp_in_blk = threadIdx.x >> 5;
    const int gwarp       = (blockIdx.x * blockDim.x + threadIdx.x) >> 5;
    const int nwarps      = (gridDim.x * blockDim.x) >> 5;

    float* out = dout + 1;

    float loss_local = 0.0f;
    int   cnt_local  = 0;

    for (int base = gwarp * 32; base < N; base += nwarps * 32) {
        // batched probe: lane i resolves row base+i
        const int myrow = base + lane;
        int my_idx = INTMAX_I;
        if (myrow < N) {
            const int taxid = __ldg(&lineages[2 * myrow + 1]);
            if ((unsigned)taxid < (unsigned)LUT_SIZE)
                my_idx = INTMAX_I - __ldg(&g_lut[taxid]);   // 0-empty -> INT_MAX
        }
        const unsigned mbits = __ballot_sync(0xFFFFFFFFu, my_idx < E);
        const int c_idx = min(my_idx, E - 1);               // safe gather index

        if (base + 32 <= N) {
            if (lane == 0) cnt_local += __popc(mbits);

            #pragma unroll 1
            for (int sub = 0; sub < 8; sub++) {
                const float* a = inputs + (size_t)(base + sub * 4) * 65;
                float*       o = out    + (size_t)(base + sub * 4) * 65;

                float p[4];
                #pragma unroll
                for (int j = 0; j < 4; j++) {
                    const int  jj = sub * 4 + j;
                    const bool m  = (mbits >> jj) & 1u;
                    const int idx = __shfl_sync(0xFFFFFFFFu, c_idx, jj);
                    const float* q = g_qcache + (size_t)idx * 65;

                    const float a0 = __ldg(&a[0]);
                    const float aA = __ldg(&a[1 + lane]);
                    const float aB = __ldg(&a[33 + lane]);
                    const float q0 = __ldg(&q[0]);
                    const float qA = __ldg(&q[1 + lane]);
                    const float qB = __ldg(&q[33 + lane]);

                    // p sums to dot - q0*a0 = -mlip (correction on lane 0 only)
                    float t = qA * aA + qB * aB;
                    if (lane == 0) t -= q0 * a0;
                    p[j] = t;

                    if (lane == 0) o[0] = m ? q0 : a0;
                    o[1 + lane]  = m ? qA : aA;
                    o[33 + lane] = m ? qB : aB;

                    a += 65;
                    o += 65;
                }

                // transpose-reduce: 4 vals x 32 lanes -> lane l holds row (l>>3)
                #pragma unroll
                for (int i = 0; i < 2; i++) {
                    float send = (lane & 16) ? p[i] : p[i + 2];
                    float r = __shfl_xor_sync(0xFFFFFFFFu, send, 16);
                    p[i] = ((lane & 16) ? p[i + 2] : p[i]) + r;
                }
                {
                    float send = (lane & 8) ? p[0] : p[1];
                    float r = __shfl_xor_sync(0xFFFFFFFFu, send, 8);
                    p[0] = ((lane & 8) ? p[1] : p[0]) + r;
                }
                p[0] += __shfl_xor_sync(0xFFFFFFFFu, p[0], 4);
                p[0] += __shfl_xor_sync(0xFFFFFFFFu, p[0], 2);
                p[0] += __shfl_xor_sync(0xFFFFFFFFu, p[0], 1);

                // lane 8j (j = lane>>3) adds acosh for masked row
                const int  j  = lane >> 3;
                const bool mr = (mbits >> (sub * 4 + j)) & 1u;
                if ((lane & 7) == 0 && mr)
                    loss_local += acoshf(fmaxf(-p[0], 1.0f + EPS));
            }
        } else {
            // tail path (rare): per-row scalar
            const int nrows = N - base;
            for (int jr = 0; jr < nrows; jr++) {
                const int  row  = base + jr;
                const bool m    = (mbits >> jr) & 1u;
                const float* a = inputs + (size_t)row * 65;
                float*       o = out    + (size_t)row * 65;

                const float a0 = __ldg(&a[0]);
                const float aA = __ldg(&a[1 + lane]);
                const float aB = __ldg(&a[33 + lane]);

                if (m) {
                    const int idx = __shfl_sync(0xFFFFFFFFu, c_idx, jr);
                    const float* q = g_qcache + (size_t)idx * 65;
                    const float q0 = __ldg(&q[0]);
                    const float qA = __ldg(&q[1 + lane]);
                    const float qB = __ldg(&q[33 + lane]);

                    float dot = qA * aA + qB * aB;
                    #pragma unroll
                    for (int off = 16; off; off >>= 1)
                        dot += __shfl_xor_sync(0xFFFFFFFFu, dot, off);

                    if (lane == 0) {
                        loss_local += acoshf(fmaxf(q0 * a0 - dot, 1.0f + EPS));
                        cnt_local  += 1;
                        o[0] = q0;
                    }
                    o[1 + lane]  = qA;
                    o[33 + lane] = qB;
                } else {
                    if (lane == 0) o[0] = a0;
                    o[1 + lane]  = aA;
                    o[33 + lane] = aB;
                }
            }
        }
    }

    // warp reduce, block reduce, one atomic pair per block, ticket finalize
    #pragma unroll
    for (int off = 16; off; off >>= 1) {
        loss_local += __shfl_xor_sync(0xFFFFFFFFu, loss_local, off);
        cnt_local  += __shfl_xor_sync(0xFFFFFFFFu, cnt_local, off);
    }
    __shared__ float s_loss[8];
    __shared__ int   s_cnt[8];
    if (lane == 0) { s_loss[warp_in_blk] = loss_local; s_cnt[warp_in_blk] = cnt_local; }
    __syncthreads();
    if (threadIdx.x == 0) {
        float bl = 0.0f; int bc = 0;
        for (int i = 0; i < 8; i++) { bl += s_loss[i]; bc += s_cnt[i]; }
        atomicAdd(&g_loss_sum, (double)bl);
        atomicAdd(&g_valid_cnt, bc);

        __threadfence();
        unsigned t = atomicAdd(&g_done, 1u);
        if ((t % (unsigned)gridDim.x) == (unsigned)gridDim.x - 1u) {
            double ls = atomicAdd(&g_loss_sum, 0.0);
            int    vc = atomicAdd(&g_valid_cnt, 0);
            double nv = (vc < 1) ? 1.0 : (double)vc;
            dout[0] = (float)((double)COMMIT_SCALE * ls / nv);
            g_loss_sum  = 0.0;
            g_valid_cnt = 0;
        }
    }
}

extern "C" void kernel_launch(void* const* d_in, const int* in_sizes, int n_in,
                              void* d_out, int out_size) {
    const float* inputs   = (const float*)d_in[0];
    const int*   lineages = (const int*)  d_in[1];
    const float* emb      = (const float*)d_in[2];
    const int*   key      = (const int*)  d_in[3];

    const int N = in_sizes[1] / 2;
    int E = in_sizes[3];
    if (E > E_MAX) E = E_MAX;

    float* out = (float*)d_out;

    vq_codebook_kernel<<<MAIN_BLOCKS, 256>>>(emb, key, E);
    vq_main_kernel<<<MAIN_BLOCKS, 256>>>(inputs, lineages, out, N, E);
}

// round 16
// speedup vs baseline: 1.0200x; 1.0200x over previous
#include <cuda_runtime.h>
#include <math.h>

#define COMMIT_SCALE 1.25f   // 1 + COMMITMENT_COST; e_latent == q_latent in forward
#define EPS 1e-6f

#define LUT_SIZE 262144      // taxid range [0, 2E) = [0, 100000)
#define E_MAX    50016
#define INTMAX_I 0x7FFFFFFF

// g_lut: 0-as-empty encoding (stored = INT_MAX - idx; atomicMax == lower_bound).
// Zero-init at module load; idempotent across graph replays.
__device__ int    g_lut[LUT_SIZE];
__device__ float  g_qcache[E_MAX * 65];   // [E][65] = exact masked output row
__device__ double g_loss_sum;             // reset by finalize each replay
__device__ int    g_valid_cnt;
__device__ unsigned g_done;               // monotonic last-block ticket

__device__ __forceinline__ float tanh_approx(float x) {
    float r;
    asm("tanh.approx.f32 %0, %1;" : "=f"(r) : "f"(x));
    return r;
}

__device__ __forceinline__ void prefetch_l2(const void* p) {
    asm volatile("prefetch.global.L2 [%0];" :: "l"(p));
}

// ---------------- K1: codebook (approx transcendentals) + key scatter ----------------
__global__ void __launch_bounds__(256) vq_codebook_kernel(
    const float* __restrict__ emb, const int* __restrict__ key, int E)
{
    const int tid = blockIdx.x * blockDim.x + threadIdx.x;
    const int nth = gridDim.x * blockDim.x;

    for (int i = tid; i < E; i += nth) {
        int v = key[i];
        if (v >= 0 && v < LUT_SIZE) atomicMax(&g_lut[v], INTMAX_I - i);
    }

    const int lane = threadIdx.x & 31;
    const int gw = tid >> 5, nw = nth >> 5;
    for (int e = gw; e < E; e += nw) {
        const float wA = __ldg(&emb[(size_t)e * 64 + lane]);
        const float wB = __ldg(&emb[(size_t)e * 64 + lane + 32]);
        const float xA = 3.0f * tanh_approx(wA);
        const float xB = 3.0f * tanh_approx(wB);

        float s = xA * xA + xB * xB;
        #pragma unroll
        for (int off = 16; off; off >>= 1)
            s += __shfl_xor_sync(0xFFFFFFFFu, s, off);

        float n = sqrtf(fmaxf(s, EPS));
        n = fminf(n, 10.0f);
        const float en  = __expf(n);
        const float emn = __fdividef(1.0f, en);
        const float ch  = 0.5f * (en + emn);
        const float sh  = __fdividef(0.5f * (en - emn), n);

        float* q = g_qcache + (size_t)e * 65;
        if (lane == 0) q[0] = ch;
        q[1 + lane]  = sh * xA;
        q[33 + lane] = sh * xB;
    }
}

// ---------------- K2: main — 4-row subtiles + transpose-reduce + L2 prefetch ----------------
__global__ void __launch_bounds__(256, 7) vq_main_kernel(
    const float* __restrict__ inputs,    // [N, 65]
    const int*   __restrict__ lineages,  // [N, 2]
    float*       __restrict__ dout,      // [0]=loss, +1 = quantized_all
    int N, int E)
{
    const int lane        = threadIdx.x & 31;
    const int warp_in_blk = threadIdx.x >> 5;
    const int gwarp       = (blockIdx.x * blockDim.x + threadIdx.x) >> 5;
    const int nwarps      = (gridDim.x * blockDim.x) >> 5;

    float* out = dout + 1;

    float loss_local = 0.0f;
    int   cnt_local  = 0;

    for (int base = gwarp * 32; base < N; base += nwarps * 32) {
        // ---- L2 prefetch of the NEXT tile (fire-and-forget, no registers) ----
        {
            const int nb = base + nwarps * 32;
            if (nb + 32 <= N) {
                const char* pa = (const char*)(inputs + (size_t)nb * 65);
                prefetch_l2(pa + (size_t)lane * 128);          // lines 0..31
                prefetch_l2(pa + (size_t)(lane + 32) * 128);   // lines 32..63
                if (lane == 0) prefetch_l2(pa + (size_t)64 * 128);  // line 64
                if (lane < 2)
                    prefetch_l2((const char*)(lineages + (size_t)nb * 2) + lane * 128);
            }
        }

        // batched probe: lane i resolves row base+i
        const int myrow = base + lane;
        int my_idx = INTMAX_I;
        if (myrow < N) {
            const int taxid = __ldg(&lineages[2 * myrow + 1]);
            if ((unsigned)taxid < (unsigned)LUT_SIZE)
                my_idx = INTMAX_I - __ldg(&g_lut[taxid]);   // 0-empty -> INT_MAX
        }
        const unsigned mbits = __ballot_sync(0xFFFFFFFFu, my_idx < E);
        const int c_idx = min(my_idx, E - 1);               // safe gather index

        if (base + 32 <= N) {
            if (lane == 0) cnt_local += __popc(mbits);

            #pragma unroll 1
            for (int sub = 0; sub < 8; sub++) {
                const float* a = inputs + (size_t)(base + sub * 4) * 65;
                float*       o = out    + (size_t)(base + sub * 4) * 65;

                float p[4];
                #pragma unroll
                for (int j = 0; j < 4; j++) {
                    const int  jj = sub * 4 + j;
                    const bool m  = (mbits >> jj) & 1u;
                    const int idx = __shfl_sync(0xFFFFFFFFu, c_idx, jj);
                    const float* q = g_qcache + (size_t)idx * 65;

                    const float a0 = __ldg(&a[0]);
                    const float aA = __ldg(&a[1 + lane]);
                    const float aB = __ldg(&a[33 + lane]);
                    const float q0 = __ldg(&q[0]);
                    const float qA = __ldg(&q[1 + lane]);
                    const float qB = __ldg(&q[33 + lane]);

                    // p sums to dot - q0*a0 = -mlip (correction on lane 0 only)
                    float t = qA * aA + qB * aB;
                    if (lane == 0) t -= q0 * a0;
                    p[j] = t;

                    if (lane == 0) o[0] = m ? q0 : a0;
                    o[1 + lane]  = m ? qA : aA;
                    o[33 + lane] = m ? qB : aB;

                    a += 65;
                    o += 65;
                }

                // transpose-reduce: 4 vals x 32 lanes -> lane l holds row (l>>3)
                #pragma unroll
                for (int i = 0; i < 2; i++) {
                    float send = (lane & 16) ? p[i] : p[i + 2];
                    float r = __shfl_xor_sync(0xFFFFFFFFu, send, 16);
                    p[i] = ((lane & 16) ? p[i + 2] : p[i]) + r;
                }
                {
                    float send = (lane & 8) ? p[0] : p[1];
                    float r = __shfl_xor_sync(0xFFFFFFFFu, send, 8);
                    p[0] = ((lane & 8) ? p[1] : p[0]) + r;
                }
                p[0] += __shfl_xor_sync(0xFFFFFFFFu, p[0], 4);
                p[0] += __shfl_xor_sync(0xFFFFFFFFu, p[0], 2);
                p[0] += __shfl_xor_sync(0xFFFFFFFFu, p[0], 1);

                // lane 8j (j = lane>>3) adds acosh for masked row
                const int  j  = lane >> 3;
                const bool mr = (mbits >> (sub * 4 + j)) & 1u;
                if ((lane & 7) == 0 && mr)
                    loss_local += acoshf(fmaxf(-p[0], 1.0f + EPS));
            }
        } else {
            // tail path (rare): per-row scalar
            const int nrows = N - base;
            for (int jr = 0; jr < nrows; jr++) {
                const int  row  = base + jr;
                const bool m    = (mbits >> jr) & 1u;
                const float* a = inputs + (size_t)row * 65;
                float*       o = out    + (size_t)row * 65;

                const float a0 = __ldg(&a[0]);
                const float aA = __ldg(&a[1 + lane]);
                const float aB = __ldg(&a[33 + lane]);

                if (m) {
                    const int idx = __shfl_sync(0xFFFFFFFFu, c_idx, jr);
                    const float* q = g_qcache + (size_t)idx * 65;
                    const float q0 = __ldg(&q[0]);
                    const float qA = __ldg(&q[1 + lane]);
                    const float qB = __ldg(&q[33 + lane]);

                    float dot = qA * aA + qB * aB;
                    #pragma unroll
                    for (int off = 16; off; off >>= 1)
                        dot += __shfl_xor_sync(0xFFFFFFFFu, dot, off);

                    if (lane == 0) {
                        loss_local += acoshf(fmaxf(q0 * a0 - dot, 1.0f + EPS));
                        cnt_local  += 1;
                        o[0] = q0;
                    }
                    o[1 + lane]  = qA;
                    o[33 + lane] = qB;
                } else {
                    if (lane == 0) o[0] = a0;
                    o[1 + lane]  = aA;
                    o[33 + lane] = aB;
                }
            }
        }
    }

    // warp reduce, block reduce, one atomic pair per block, ticket finalize
    #pragma unroll
    for (int off = 16; off; off >>= 1) {
        loss_local += __shfl_xor_sync(0xFFFFFFFFu, loss_local, off);
        cnt_local  += __shfl_xor_sync(0xFFFFFFFFu, cnt_local, off);
    }
    __shared__ float s_loss[8];
    __shared__ int   s_cnt[8];
    if (lane == 0) { s_loss[warp_in_blk] = loss_local; s_cnt[warp_in_blk] = cnt_local; }
    __syncthreads();
    if (threadIdx.x == 0) {
        float bl = 0.0f; int bc = 0;
        for (int i = 0; i < 8; i++) { bl += s_loss[i]; bc += s_cnt[i]; }
        atomicAdd(&g_loss_sum, (double)bl);
        atomicAdd(&g_valid_cnt, bc);

        __threadfence();
        unsigned t = atomicAdd(&g_done, 1u);
        if ((t % (unsigned)gridDim.x) == (unsigned)gridDim.x - 1u) {
            double ls = atomicAdd(&g_loss_sum, 0.0);
            int    vc = atomicAdd(&g_valid_cnt, 0);
            double nv = (vc < 1) ? 1.0 : (double)vc;
            dout[0] = (float)((double)COMMIT_SCALE * ls / nv);
            g_loss_sum  = 0.0;
            g_valid_cnt = 0;
        }
    }
}

extern "C" void kernel_launch(void* const* d_in, const int* in_sizes, int n_in,
                              void* d_out, int out_size) {
    const float* inputs   = (const float*)d_in[0];
    const int*   lineages = (const int*)  d_in[1];
    const float* emb      = (const float*)d_in[2];
    const int*   key      = (const int*)  d_in[3];

    const int N = in_sizes[1] / 2;
    int E = in_sizes[3];
    if (E > E_MAX) E = E_MAX;

    float* out = (float*)d_out;

    vq_codebook_kernel<<<2048, 256>>>(emb, key, E);
    vq_main_kernel<<<2048, 256>>>(inputs, lineages, out, N, E);
}